// round 3
// baseline (speedup 1.0000x reference)
#include <cuda_runtime.h>
#include <cuda_bf16.h>
#include <cstdint>

#define CH   512
#define HW   4096

__device__ __align__(16) __nv_bfloat16 g_feats[CH * HW];   // 4 MB bf16 feats
__device__ __align__(16) float         g_G[CH * CH];       // 1 MB gram (scaled by 1/2^20)
__device__ __align__(16) float         g_S[1024 * 512];    // 2 MB partial S rows
__device__ float g_sumT2;

#define SCALE (1.0e6f / 33554432.0f)

// ---------------------------------------------------------------------------
// Kernel 1: fp32 -> bf16 convert, zero G / sumT2 / out
// ---------------------------------------------------------------------------
__global__ void __launch_bounds__(256) k_convert(const float* __restrict__ x,
                                                 float* __restrict__ out) {
    const int gi = blockIdx.x * 256 + threadIdx.x;   // 131072 threads, 4 float4 each
    const float4* xv = reinterpret_cast<const float4*>(x);
    uint2* fv = reinterpret_cast<uint2*>(g_feats);
    float4 v[4];
    #pragma unroll
    for (int u = 0; u < 4; u++) v[u] = xv[gi + u * 131072];
    #pragma unroll
    for (int u = 0; u < 4; u++) {
        __nv_bfloat162 p0, p1;
        p0.x = __float2bfloat16(v[u].x); p0.y = __float2bfloat16(v[u].y);
        p1.x = __float2bfloat16(v[u].z); p1.y = __float2bfloat16(v[u].w);
        uint2 pk;
        pk.x = *reinterpret_cast<uint32_t*>(&p0);
        pk.y = *reinterpret_cast<uint32_t*>(&p1);
        fv[gi + u * 131072] = pk;
    }
    if (gi < 65536) {   // zero G (split-K atomics need it)
        reinterpret_cast<float4*>(g_G)[gi] = make_float4(0.f, 0.f, 0.f, 0.f);
    }
    if (gi == 0) { out[0] = 0.0f; g_sumT2 = 0.0f; }
}

// ---------------------------------------------------------------------------
// Kernel 2 (fat): blocks 0..71 -> symmetric GEMM tiles (36 tiles x splitK 2)
//                 blocks 72+   -> stream T computing S[r,c] rows and sumT2
// ---------------------------------------------------------------------------
__device__ __forceinline__ uint32_t smem_u32(const void* p) {
    return static_cast<uint32_t>(__cvta_generic_to_shared(p));
}
__device__ __forceinline__ void cp_async16(uint32_t dst, const void* src) {
    asm volatile("cp.async.cg.shared.global [%0], [%1], 16;\n" :: "r"(dst), "l"(src));
}
__device__ __forceinline__ void ldm_x4(uint32_t* d, uint32_t addr) {
    asm volatile("ldmatrix.sync.aligned.m8n8.x4.shared.b16 {%0,%1,%2,%3}, [%4];"
                 : "=r"(d[0]), "=r"(d[1]), "=r"(d[2]), "=r"(d[3]) : "r"(addr));
}
__device__ __forceinline__ void mma_bf16(float* c, const uint32_t* a, uint32_t b0, uint32_t b1) {
    asm volatile("mma.sync.aligned.m16n8k16.row.col.f32.bf16.bf16.f32 "
                 "{%0,%1,%2,%3},{%4,%5,%6,%7},{%8,%9},{%0,%1,%2,%3};"
                 : "+f"(c[0]), "+f"(c[1]), "+f"(c[2]), "+f"(c[3])
                 : "r"(a[0]), "r"(a[1]), "r"(a[2]), "r"(a[3]), "r"(b0), "r"(b1));
}

// smem layout (byte offsets into sm[]):
//  gemm: A stage0 @0, A stage1 @9216, B stage0 @18432, B stage1 @27648 (rows of 144B)
//  loss: warp-private sS[8][512] @0 (16384B), red[256] @16384
#define SM_BYTES 36864

__global__ void __launch_bounds__(256) k_fat(const float* __restrict__ target) {
    __shared__ __align__(16) char sm[SM_BYTES + 1024];
    const int t = threadIdx.x;
    const int w = t >> 5, l = t & 31;

    if (blockIdx.x < 72) {
        // ---------------- GEMM path ----------------
        const int tile = blockIdx.x % 36;
        const int kz   = (blockIdx.x / 36) * 2048;
        int rem = tile, bi = 0;
        while (rem >= 8 - bi) { rem -= 8 - bi; bi++; }
        const int bj = bi + rem;
        const int m0 = bi * 64, n0 = bj * 64;

        const int wm = (w >> 2) * 32;       // warp m offset (0/32)
        const int wn = (w & 3) * 16;        // warp n offset (0..48)

        float acc[2][2][4];
        #pragma unroll
        for (int a = 0; a < 2; a++)
          #pragma unroll
          for (int h = 0; h < 2; h++)
            #pragma unroll
            for (int q = 0; q < 4; q++) acc[a][h][q] = 0.f;

        const int lr = t >> 3;            // 0..31 (row group; +32 second half)
        const int lc = (t & 7) * 8;       // bf16 col of 16B chunk
        const int lrow = l & 15;
        const int lkh  = (l >> 4) * 8;

        auto load_stage = [&](int ks, int buf) {
            const int kb = kz + ks * 64;
            char* Ab = sm + buf * 9216;
            char* Bb = sm + 18432 + buf * 9216;
            #pragma unroll
            for (int p = 0; p < 2; p++) {
                const int row = lr + p * 32;
                cp_async16(smem_u32(Ab + row * 144 + lc * 2),
                           &g_feats[(m0 + row) * HW + kb + lc]);
                cp_async16(smem_u32(Bb + row * 144 + lc * 2),
                           &g_feats[(n0 + row) * HW + kb + lc]);
            }
            asm volatile("cp.async.commit_group;\n" ::: "memory");
        };

        load_stage(0, 0);
        for (int ks = 0; ks < 32; ks++) {
            const int buf = ks & 1;
            if (ks < 31) {
                load_stage(ks + 1, buf ^ 1);
                asm volatile("cp.async.wait_group 1;\n" ::: "memory");
            } else {
                asm volatile("cp.async.wait_group 0;\n" ::: "memory");
            }
            __syncthreads();

            char* Ab = sm + buf * 9216;
            char* Bb = sm + 18432 + buf * 9216;
            #pragma unroll
            for (int k16 = 0; k16 < 4; k16++) {
                uint32_t afr[2][4], bfr[4];
                #pragma unroll
                for (int mt = 0; mt < 2; mt++)
                    ldm_x4(afr[mt], smem_u32(Ab + (wm + mt * 16 + lrow) * 144
                                                + (k16 * 16 + lkh) * 2));
                ldm_x4(bfr, smem_u32(Bb + (wn + lrow) * 144 + (k16 * 16 + lkh) * 2));
                #pragma unroll
                for (int mt = 0; mt < 2; mt++) {
                    mma_bf16(acc[mt][0], afr[mt], bfr[0], bfr[2]);
                    mma_bf16(acc[mt][1], afr[mt], bfr[1], bfr[3]);
                }
            }
            __syncthreads();
        }

        const float s = 1.0f / 1048576.0f;
        const int g = l >> 2, cc = (l & 3) * 2;
        const bool mirror = (bi != bj);
        #pragma unroll
        for (int mt = 0; mt < 2; mt++)
          #pragma unroll
          for (int h = 0; h < 2; h++) {
            const int row = m0 + wm + mt * 16 + g;
            const int col = n0 + wn + h * 8 + cc;
            const float v0 = acc[mt][h][0] * s;
            const float v1 = acc[mt][h][1] * s;
            const float v2 = acc[mt][h][2] * s;
            const float v3 = acc[mt][h][3] * s;
            atomicAdd(&g_G[row * CH + col],           v0);
            atomicAdd(&g_G[row * CH + col + 1],       v1);
            atomicAdd(&g_G[(row + 8) * CH + col],     v2);
            atomicAdd(&g_G[(row + 8) * CH + col + 1], v3);
            if (mirror) {
                atomicAdd(&g_G[col * CH + row],           v0);
                atomicAdd(&g_G[(col + 1) * CH + row],     v1);
                atomicAdd(&g_G[col * CH + row + 8],       v2);
                atomicAdd(&g_G[(col + 1) * CH + row + 8], v3);
            }
          }
    } else {
        // ---------------- T-stream path: S rows + sumT2 ----------------
        const int b  = blockIdx.x - 72;   // 0..1023
        const int r  = b >> 1;
        const int j0 = (b & 1) * 128;

        float* sAll = reinterpret_cast<float*>(sm);       // [8][512]
        float* sSw  = sAll + w * 512;                     // warp-private
        float* red  = reinterpret_cast<float*>(sm + 16384);

        for (int idx = t; idx < 4096; idx += 256) sAll[idx] = 0.f;
        __syncthreads();

        float aT2 = 0.f;
        for (int jb = 0; jb < 128; jb += 8) {
            float tv[8]; int io[8];
            #pragma unroll
            for (int u = 0; u < 8; u++) {
                const int j = j0 + jb + u;
                io[u] = (r - j + 512) & 511;
                tv[u] = target[io[u] * 65536 + j * 256 + t];
            }
            #pragma unroll
            for (int u = 0; u < 8; u++) {
                aT2 = fmaf(tv[u], tv[u], aT2);
                sSw[(io[u] + t) & 511] += tv[u];
            }
        }
        __syncthreads();

        // reduce warp partitions -> global S row for this block
        #pragma unroll
        for (int c = t; c < 512; c += 256) {
            float s = 0.f;
            #pragma unroll
            for (int ww = 0; ww < 8; ww++) s += sAll[ww * 512 + c];
            g_S[b * 512 + c] = s;
        }

        red[t] = aT2;
        __syncthreads();
        #pragma unroll
        for (int s2 = 128; s2 > 0; s2 >>= 1) {
            if (t < s2) red[t] += red[t + s2];
            __syncthreads();
        }
        if (t == 0) atomicAdd(&g_sumT2, red[0]);
    }
}

// ---------------------------------------------------------------------------
// Kernel 3: combine  loss = (sumT2 - 2*sum(G*S) + sum(mult*G^2)) * SCALE
// ---------------------------------------------------------------------------
__global__ void __launch_bounds__(256) k_combine(float* __restrict__ out) {
    __shared__ float red[256];
    const int t = threadIdx.x;
    const int g = blockIdx.x * 256 + t;     // 262144 = 512*512
    const int r = g >> 9, c = g & 511;
    const float Gv = g_G[g];
    const float Sv = g_S[(2 * r) * 512 + c] + g_S[(2 * r + 1) * 512 + c];
    const int d = (r - c) & 511;
    const float mult = (float)((d <= 256) ? (256 - d) : (d - 256));
    const float term = fmaf(mult * Gv, Gv, -2.0f * Gv * Sv);

    red[t] = term;
    __syncthreads();
    #pragma unroll
    for (int s = 128; s > 0; s >>= 1) {
        if (t < s) red[t] += red[t + s];
        __syncthreads();
    }
    if (t == 0) atomicAdd(out, red[0] * SCALE);
    if (g == 0) atomicAdd(out, g_sumT2 * SCALE);
}

// ---------------------------------------------------------------------------
extern "C" void kernel_launch(void* const* d_in, const int* in_sizes, int n_in,
                              void* d_out, int out_size) {
    const float* x      = (const float*)d_in[0];   // (1,512,64,64) fp32
    const float* target = (const float*)d_in[1];   // (512,256,256) fp32
    float* out = (float*)d_out;

    k_convert<<<512, 256>>>(x, out);
    k_fat<<<72 + 1024, 256>>>(target);
    k_combine<<<1024, 256>>>(out);
}